// round 8
// baseline (speedup 1.0000x reference)
#include <cuda_runtime.h>
#include <math.h>

#define KS   9        // k-splits
#define DC   128      // d-chunk staged per iteration
#define STR  132      // smem row stride (floats): conflict-free for both phases
#define NQ   200
#define NGT  32
#define DTOT 65536
#define CHTOT (DTOT/DC)   // 512 chunks along d

// ---- scratch (static __device__, per allocation rules) ----
__device__ float g_part[KS * 4 * NQ * NGT];   // per-ksplit partial inter
__device__ float g_psum[KS * 4 * NQ];         // per-ksplit partial sigmoid row sums
__device__ float g_gtp[KS * 4 * NGT];         // per-ksplit partial gt row sums

__device__ __forceinline__ float sigf(float x) {
    return __fdividef(1.0f, 1.0f + __expf(-x));
}
__device__ __forceinline__ void ffma2(unsigned long long& d,
                                      unsigned long long a,
                                      unsigned long long b) {
    asm("fma.rn.f32x2 %0, %1, %2, %0;" : "+l"(d) : "l"(a), "l"(b));
}

extern __shared__ float sm[];

// ---------------------------------------------------------------------------
// Kernel A: sigmoid + K-split GEMM + fused row sums.
// grid(KS, 4 qtiles, 4 batches), 256 thr. Block tile 64q x 32n over 1/KS of d.
// Warp wz owns d-slice [wz*16, wz*16+16); per-thread 16q x 4n f32x2 accums
// (128 regs) with lanes = 4 qtr x 8 ntr.
// ---------------------------------------------------------------------------
__global__ void __launch_bounds__(256, 1)
kA(const float* __restrict__ pm, const float* __restrict__ gt) {
    const int ks = blockIdx.x, qt = blockIdx.y, b = blockIdx.z;
    const int q0 = qt * 64;
    const int tid = threadIdx.x;

    float* pmS = sm;                 // [64][STR]
    float* gtS = sm + 64 * STR;      // [32][STR]

    const int lane = tid & 31;
    const int wz   = tid >> 5;       // warp = d-slice 0..7
    const int qtr  = lane & 3;       // q-thread 0..3
    const int ntr  = lane >> 2;      // n-thread 0..7

    unsigned long long acc[16][4];   // 128 registers
    #pragma unroll
    for (int i = 0; i < 16; i++)
        #pragma unroll
        for (int j = 0; j < 4; j++) acc[i][j] = 0ull;

    float rowsum[8];
    #pragma unroll
    for (int i = 0; i < 8; i++) rowsum[i] = 0.f;
    float gsum[4];
    #pragma unroll
    for (int i = 0; i < 4; i++) gsum[i] = 0.f;

    // staging coords: pm row q = wz + 8*it (it 0..7), gt row n = wz + 8*it (it 0..3)
    unsigned vm = 0;
    #pragma unroll
    for (int it = 0; it < 8; it++)
        if (q0 + wz + 8 * it < NQ) vm |= 1u << it;

    const size_t pmRow = (size_t)(b * NQ + q0 + wz) * DTOT + (size_t)lane * 4;
    const size_t gtRow = (size_t)(b * NGT + wz) * DTOT + (size_t)lane * 4;

    const int c0 = (ks * CHTOT) / KS;
    const int c1 = ((ks + 1) * CHTOT) / KS;

    for (int c = c0; c < c1; c++) {
        const int kb = c * DC;

        // ---- issue all global loads first (MLP = 12) ----
        float4 rg[4];
        #pragma unroll
        for (int it = 0; it < 4; it++)
            rg[it] = *reinterpret_cast<const float4*>(
                gt + gtRow + (size_t)it * 8 * DTOT + kb);
        float4 rp[8];
        #pragma unroll
        for (int it = 0; it < 8; it++)
            if ((vm >> it) & 1)
                rp[it] = *reinterpret_cast<const float4*>(
                    pm + pmRow + (size_t)it * 8 * DTOT + kb);

        // ---- sigmoid + store pm; per-row sums accumulate in registers ----
        #pragma unroll
        for (int it = 0; it < 8; it++) {
            float4 v;
            if ((vm >> it) & 1) {
                v.x = sigf(rp[it].x); v.y = sigf(rp[it].y);
                v.z = sigf(rp[it].z); v.w = sigf(rp[it].w);
                rowsum[it] += (v.x + v.y) + (v.z + v.w);
            } else {
                v = make_float4(0.f, 0.f, 0.f, 0.f);
            }
            *reinterpret_cast<float4*>(&pmS[(wz + 8 * it) * STR + lane * 4]) = v;
        }
        #pragma unroll
        for (int it = 0; it < 4; it++) {
            gsum[it] += (rg[it].x + rg[it].y) + (rg[it].z + rg[it].w);
            *reinterpret_cast<float4*>(&gtS[(wz + 8 * it) * STR + lane * 4]) = rg[it];
        }
        __syncthreads();

        // ---- compute: warp wz covers d in [wz*16, wz*16+16) ----
        const int db = wz * 16;
        #pragma unroll
        for (int s = 0; s < 4; s++) {
            const int d = db + s * 4;
            ulonglong2 g2[4];
            #pragma unroll
            for (int j = 0; j < 4; j++)
                g2[j] = *reinterpret_cast<const ulonglong2*>(
                    &gtS[(ntr + 8 * j) * STR + d]);
            #pragma unroll
            for (int i = 0; i < 16; i++) {
                ulonglong2 p2 = *reinterpret_cast<const ulonglong2*>(
                    &pmS[(qtr + 4 * i) * STR + d]);
                #pragma unroll
                for (int j = 0; j < 4; j++) {
                    ffma2(acc[i][j], p2.x, g2[j].x);
                    ffma2(acc[i][j], p2.y, g2[j].y);
                }
            }
        }
        __syncthreads();
    }

    // ---- deterministic cross-warp reduction via smem (reuse sm[0..8191]) ----
    // output (q,n): q = qtr + 4*i, n = ntr + 8*j
    float* red = sm;   // [4][2048] floats, fits inside pmS region (8448)
    if (wz < 4) {
        #pragma unroll
        for (int i = 0; i < 16; i++)
            #pragma unroll
            for (int j = 0; j < 4; j++) {
                float2 f2 = *reinterpret_cast<float2*>(&acc[i][j]);
                red[wz * 2048 + (qtr + 4 * i) * 32 + (ntr + 8 * j)] = f2.x + f2.y;
            }
    }
    __syncthreads();
    if (wz >= 4) {
        #pragma unroll
        for (int i = 0; i < 16; i++)
            #pragma unroll
            for (int j = 0; j < 4; j++) {
                float2 f2 = *reinterpret_cast<float2*>(&acc[i][j]);
                red[(wz - 4) * 2048 + (qtr + 4 * i) * 32 + (ntr + 8 * j)] += f2.x + f2.y;
            }
    }
    __syncthreads();

    for (int o = tid; o < 2048; o += 256) {
        float s = red[o] + red[2048 + o] + red[4096 + o] + red[6144 + o];
        int q = o >> 5;
        if (q0 + q < NQ)
            g_part[((size_t)(ks * 4 + b) * NQ + q0 + q) * 32 + (o & 31)] = s;
    }

    // ---- per-q sigmoid sums (q warp-uniform per it) ----
    #pragma unroll
    for (int it = 0; it < 8; it++) {
        float s = rowsum[it];
        #pragma unroll
        for (int off = 16; off; off >>= 1)
            s += __shfl_down_sync(0xffffffffu, s, off);
        if (lane == 0 && ((vm >> it) & 1))
            g_psum[(ks * 4 + b) * NQ + q0 + wz + 8 * it] = s;
    }
    // ---- per-n gt sums (only qt==0 writes; n = wz + 8*it warp-uniform) ----
    if (qt == 0) {
        #pragma unroll
        for (int it = 0; it < 4; it++) {
            float s = gsum[it];
            #pragma unroll
            for (int off = 16; off; off >>= 1)
                s += __shfl_down_sync(0xffffffffu, s, off);
            if (lane == 0)
                g_gtp[(ks * 4 + b) * NGT + wz + 8 * it] = s;
        }
    }
}

// ---------------------------------------------------------------------------
// Kernel C: combine + per-column top-4 + greedy dedup + output. grid(4).
// OUTPUT is float32: src||tgt||valid as floats (512 each).
// ---------------------------------------------------------------------------
__global__ void __launch_bounds__(256)
kC(const float* __restrict__ logits, float* __restrict__ out) {
    const int b = blockIdx.x, tid = threadIdx.x;
    __shared__ float comb[NQ * NGT];
    __shared__ float psS[NQ], clsS[NQ], gsS[NGT];
    __shared__ int top4[NGT * 4];
    __shared__ unsigned char assigned[NQ];

    if (tid < NQ) {
        float s = 0.f;
        #pragma unroll
        for (int z = 0; z < KS; z++) s += g_psum[(z * 4 + b) * NQ + tid];
        psS[tid] = s;
        float l0 = logits[(b * NQ + tid) * 2 + 0];
        float l1 = logits[(b * NQ + tid) * 2 + 1];
        clsS[tid] = 1.0f / (1.0f + expf(l0 - l1));   // softmax(...)[1]
    }
    if (tid < NGT) {
        float s = 0.f;
        #pragma unroll
        for (int z = 0; z < KS; z++) s += g_gtp[(z * 4 + b) * NGT + tid];
        gsS[tid] = s;
    }
    __syncthreads();

    for (int o = tid; o < NQ * NGT; o += 256) {
        float inter = 0.f;
        #pragma unroll
        for (int z = 0; z < KS; z++)
            inter += g_part[(size_t)(z * 4 + b) * NQ * 32 + o];
        comb[o] = inter / (psS[o >> 5] + gsS[o & 31] - inter + 1e-6f) * clsS[o >> 5];
    }
    __syncthreads();

    // per-column top-4 (warp w handles columns 4w..4w+3); tie -> lower q
    const int w = tid >> 5, lane = tid & 31;
    for (int n = w * 4; n < w * 4 + 4; n++) {
        float v[7];
        #pragma unroll
        for (int t = 0; t < 7; t++) {
            int q = lane + 32 * t;
            v[t] = (q < NQ) ? comb[q * 32 + n] : -1e30f;
        }
        unsigned selmask = 0;
        for (int kk = 0; kk < 4; kk++) {
            float bv = -1e30f; int bq = 1 << 20;
            #pragma unroll
            for (int t = 0; t < 7; t++) {
                int q = lane + 32 * t;
                if (!((selmask >> t) & 1) && q < NQ) {
                    if (v[t] > bv || (v[t] == bv && q < bq)) { bv = v[t]; bq = q; }
                }
            }
            for (int off = 16; off; off >>= 1) {
                float ov = __shfl_xor_sync(0xffffffffu, bv, off);
                int   oq = __shfl_xor_sync(0xffffffffu, bq, off);
                if (ov > bv || (ov == bv && oq < bq)) { bv = ov; bq = oq; }
            }
            if (lane == 0) top4[n * 4 + kk] = bq;
            if ((bq & 31) == lane) selmask |= 1u << (bq >> 5);
        }
    }
    __syncthreads();

    // greedy dedup across GT columns (serial, matches reference scan order)
    if (tid == 0) {
        for (int q = 0; q < NQ; q++) assigned[q] = 0;
        for (int n = 0; n < NGT; n++)
            for (int kk = 0; kk < 4; kk++) {
                int idx = top4[n * 4 + kk];
                int sel = assigned[idx] ? -1 : idx;
                assigned[idx] = 1;
                int o = (b * NGT + n) * 4 + kk;
                out[o]        = (float)sel;                    // src_idx
                out[512 + o]  = (sel >= 0) ? (float)n : -1.0f; // tgt_idx
                out[1024 + o] = (sel >= 0) ? 1.0f : 0.0f;      // valid
            }
    }
}

extern "C" void kernel_launch(void* const* d_in, const int* in_sizes, int n_in,
                              void* d_out, int out_size) {
    const float* pm = (const float*)d_in[0];   // [4,200,256,256]
    const float* lg = (const float*)d_in[1];   // [4,200,2]
    const float* gt = (const float*)d_in[2];   // [4,32,256,256]
    float* out = (float*)d_out;

    const int smemA = (96 * STR) * sizeof(float);  // 50688 B
    cudaFuncSetAttribute(kA, cudaFuncAttributeMaxDynamicSharedMemorySize, smemA);

    kA<<<dim3(KS, 4, 4), 256, smemA>>>(pm, gt);
    kC<<<4, 256>>>(lg, out);
}

// round 9
// speedup vs baseline: 1.6379x; 1.6379x over previous
#include <cuda_runtime.h>
#include <math.h>

#define KS   9        // k-splits
#define DC   128      // d-chunk staged per iteration
#define STR  132      // smem row stride (floats): conflict-free both phases
#define NQ   200
#define NGT  32
#define DTOT 65536
#define CHTOT (DTOT/DC)   // 512 chunks along d

// ---- scratch (static __device__, per allocation rules) ----
__device__ float g_part[KS * 4 * NQ * NGT];   // per-ksplit partial inter
__device__ float g_psum[KS * 4 * NQ];         // per-ksplit sigmoid row sums
__device__ float g_gtp[KS * 4 * NGT];         // per-ksplit gt row sums

__device__ __forceinline__ float sigf(float x) {
    return __fdividef(1.0f, 1.0f + __expf(-x));
}
__device__ __forceinline__ void ffma2(unsigned long long& d,
                                      unsigned long long a,
                                      unsigned long long b) {
    asm("fma.rn.f32x2 %0, %1, %2, %0;" : "+l"(d) : "l"(a), "l"(b));
}

extern __shared__ float sm[];

// ---------------------------------------------------------------------------
// Kernel A: sigmoid + K-split GEMM + fused row sums.
// grid(KS, 4 qtiles, 4 batches), 256 thr. Block tile 64q x 32n over 1/KS of d.
// Warp w: d-slice wd = w&3 (32 d each), n-half wn = w>>2 (16 n each).
// Lanes: qtr = lane&7, ntr = lane>>3. Per-thread tile 8q x 4n f32x2 (64 regs).
// Register-prefetch pipeline hides DRAM latency under compute.
// ---------------------------------------------------------------------------
__global__ void __launch_bounds__(256, 1)
kA(const float* __restrict__ pm, const float* __restrict__ gt) {
    const int ks = blockIdx.x, qt = blockIdx.y, b = blockIdx.z;
    const int q0 = qt * 64;
    const int tid = threadIdx.x;

    float* pmS = sm;                 // [64][STR]
    float* gtS = sm + 64 * STR;      // [32][STR]

    const int lane = tid & 31;
    const int w    = tid >> 5;
    const int wd   = w & 3;          // d-slice 0..3 (32 d each)
    const int wn   = w >> 2;         // n-half 0..1 (16 n each)
    const int qtr  = lane & 7;       // q-thread 0..7
    const int ntr  = lane >> 3;      // n-thread 0..3

    unsigned long long acc[8][4];    // 64 registers
    #pragma unroll
    for (int i = 0; i < 8; i++)
        #pragma unroll
        for (int j = 0; j < 4; j++) acc[i][j] = 0ull;

    float rowsum[8];
    #pragma unroll
    for (int i = 0; i < 8; i++) rowsum[i] = 0.f;
    float gsum[4];
    #pragma unroll
    for (int i = 0; i < 4; i++) gsum[i] = 0.f;

    // staging: warp w stages pm rows w+8*it (it 0..7), gt rows w+8*it (it 0..3),
    // columns lane*4..lane*4+3 (one float4)
    unsigned vm = 0;
    #pragma unroll
    for (int it = 0; it < 8; it++)
        if (q0 + w + 8 * it < NQ) vm |= 1u << it;

    const size_t pmRow = (size_t)(b * NQ + q0 + w) * DTOT + (size_t)lane * 4;
    const size_t gtRow = (size_t)(b * NGT + w) * DTOT + (size_t)lane * 4;

    const int c0 = (ks * CHTOT) / KS;
    const int c1 = ((ks + 1) * CHTOT) / KS;

    float4 rg[4], rp[8];
    {   // preload chunk c0
        const int kb = c0 * DC;
        #pragma unroll
        for (int it = 0; it < 4; it++)
            rg[it] = *reinterpret_cast<const float4*>(
                gt + gtRow + (size_t)it * 8 * DTOT + kb);
        #pragma unroll
        for (int it = 0; it < 8; it++)
            if ((vm >> it) & 1)
                rp[it] = *reinterpret_cast<const float4*>(
                    pm + pmRow + (size_t)it * 8 * DTOT + kb);
    }

    for (int c = c0; c < c1; c++) {
        // ---- stage current chunk to smem (consumes rp/rg) ----
        #pragma unroll
        for (int it = 0; it < 8; it++) {
            float4 v;
            if ((vm >> it) & 1) {
                v.x = sigf(rp[it].x); v.y = sigf(rp[it].y);
                v.z = sigf(rp[it].z); v.w = sigf(rp[it].w);
                rowsum[it] += (v.x + v.y) + (v.z + v.w);
            } else {
                v = make_float4(0.f, 0.f, 0.f, 0.f);
            }
            *reinterpret_cast<float4*>(&pmS[(w + 8 * it) * STR + lane * 4]) = v;
        }
        #pragma unroll
        for (int it = 0; it < 4; it++) {
            gsum[it] += (rg[it].x + rg[it].y) + (rg[it].z + rg[it].w);
            *reinterpret_cast<float4*>(&gtS[(w + 8 * it) * STR + lane * 4]) = rg[it];
        }
        __syncthreads();

        // ---- prefetch next chunk into registers (flies during compute) ----
        if (c + 1 < c1) {
            const int kb = (c + 1) * DC;
            #pragma unroll
            for (int it = 0; it < 4; it++)
                rg[it] = *reinterpret_cast<const float4*>(
                    gt + gtRow + (size_t)it * 8 * DTOT + kb);
            #pragma unroll
            for (int it = 0; it < 8; it++)
                if ((vm >> it) & 1)
                    rp[it] = *reinterpret_cast<const float4*>(
                        pm + pmRow + (size_t)it * 8 * DTOT + kb);
        }

        // ---- compute: warp covers d in [wd*32, wd*32+32), n-half wn ----
        const int db = wd * 32;
        #pragma unroll
        for (int s = 0; s < 8; s++) {
            const int d = db + s * 4;
            ulonglong2 g2[4];
            #pragma unroll
            for (int j = 0; j < 4; j++)
                g2[j] = *reinterpret_cast<const ulonglong2*>(
                    &gtS[(wn * 16 + ntr + 4 * j) * STR + d]);
            #pragma unroll
            for (int i = 0; i < 8; i++) {
                ulonglong2 p2 = *reinterpret_cast<const ulonglong2*>(
                    &pmS[(qtr + 8 * i) * STR + d]);
                #pragma unroll
                for (int j = 0; j < 4; j++) {
                    ffma2(acc[i][j], p2.x, g2[j].x);
                    ffma2(acc[i][j], p2.y, g2[j].y);
                }
            }
        }
        __syncthreads();
    }

    // ---- deterministic cross-warp reduction via smem ----
    // all 8 warps write disjoint (wd, q, n) cells; then sum over wd
    float* red = sm;   // [4][2048] floats (8192 <= 64*STR)
    #pragma unroll
    for (int i = 0; i < 8; i++)
        #pragma unroll
        for (int j = 0; j < 4; j++) {
            float2 f2 = *reinterpret_cast<float2*>(&acc[i][j]);
            red[wd * 2048 + (qtr + 8 * i) * 32 + (wn * 16 + ntr + 4 * j)] =
                f2.x + f2.y;
        }
    __syncthreads();

    for (int o = tid; o < 2048; o += 256) {
        float s = red[o] + red[2048 + o] + red[4096 + o] + red[6144 + o];
        int q = o >> 5;
        if (q0 + q < NQ)
            g_part[((size_t)(ks * 4 + b) * NQ + q0 + q) * 32 + (o & 31)] = s;
    }

    // ---- per-q sigmoid sums (q = w + 8*it is warp-uniform) ----
    #pragma unroll
    for (int it = 0; it < 8; it++) {
        float s = rowsum[it];
        #pragma unroll
        for (int off = 16; off; off >>= 1)
            s += __shfl_down_sync(0xffffffffu, s, off);
        if (lane == 0 && ((vm >> it) & 1))
            g_psum[(ks * 4 + b) * NQ + q0 + w + 8 * it] = s;
    }
    // ---- per-n gt sums (qt==0 blocks only; n = w + 8*it warp-uniform) ----
    if (qt == 0) {
        #pragma unroll
        for (int it = 0; it < 4; it++) {
            float s = gsum[it];
            #pragma unroll
            for (int off = 16; off; off >>= 1)
                s += __shfl_down_sync(0xffffffffu, s, off);
            if (lane == 0)
                g_gtp[(ks * 4 + b) * NGT + w + 8 * it] = s;
        }
    }
}

// ---------------------------------------------------------------------------
// Kernel C: combine + per-column top-4 + parallel dedup + output. grid(4).
// OUTPUT is float32: src||tgt||valid as floats (512 each).
// ---------------------------------------------------------------------------
__global__ void __launch_bounds__(256)
kC(const float* __restrict__ logits, float* __restrict__ out) {
    const int b = blockIdx.x, tid = threadIdx.x;
    __shared__ float comb[NQ * NGT];
    __shared__ float psS[NQ], clsS[NQ], gsS[NGT];
    __shared__ int top4[NGT * 4];

    if (tid < NQ) {
        float s = 0.f;
        #pragma unroll
        for (int z = 0; z < KS; z++) s += g_psum[(z * 4 + b) * NQ + tid];
        psS[tid] = s;
        float l0 = logits[(b * NQ + tid) * 2 + 0];
        float l1 = logits[(b * NQ + tid) * 2 + 1];
        clsS[tid] = 1.0f / (1.0f + expf(l0 - l1));   // softmax(...)[1]
    }
    if (tid < NGT) {
        float s = 0.f;
        #pragma unroll
        for (int z = 0; z < KS; z++) s += g_gtp[(z * 4 + b) * NGT + tid];
        gsS[tid] = s;
    }
    __syncthreads();

    for (int o = tid; o < NQ * NGT; o += 256) {
        float inter = 0.f;
        #pragma unroll
        for (int z = 0; z < KS; z++)
            inter += g_part[(size_t)(z * 4 + b) * NQ * 32 + o];
        comb[o] = inter / (psS[o >> 5] + gsS[o & 31] - inter + 1e-6f) * clsS[o >> 5];
    }
    __syncthreads();

    // per-column top-4 (warp w handles columns 4w..4w+3); tie -> lower q
    const int w = tid >> 5, lane = tid & 31;
    for (int n = w * 4; n < w * 4 + 4; n++) {
        float v[7];
        #pragma unroll
        for (int t = 0; t < 7; t++) {
            int q = lane + 32 * t;
            v[t] = (q < NQ) ? comb[q * 32 + n] : -1e30f;
        }
        unsigned selmask = 0;
        for (int kk = 0; kk < 4; kk++) {
            float bv = -1e30f; int bq = 1 << 20;
            #pragma unroll
            for (int t = 0; t < 7; t++) {
                int q = lane + 32 * t;
                if (!((selmask >> t) & 1) && q < NQ) {
                    if (v[t] > bv || (v[t] == bv && q < bq)) { bv = v[t]; bq = q; }
                }
            }
            for (int off = 16; off; off >>= 1) {
                float ov = __shfl_xor_sync(0xffffffffu, bv, off);
                int   oq = __shfl_xor_sync(0xffffffffu, bq, off);
                if (ov > bv || (ov == bv && oq < bq)) { bv = ov; bq = oq; }
            }
            if (lane == 0) top4[n * 4 + kk] = bq;
            if ((bq & 31) == lane) selmask |= 1u << (bq >> 5);
        }
    }
    __syncthreads();

    // parallel dedup: slot s=(n,kk) invalid iff q appears in an earlier COLUMN
    // (within-column top-k indices are distinct, so scanning all earlier slots
    //  of earlier columns exactly matches the reference greedy scan)
    if (tid < NGT * 4) {
        int q = top4[tid];
        int n = tid >> 2;
        bool dup = false;
        for (int sp = 0; sp < (n << 2); sp++) dup |= (top4[sp] == q);
        int sel = dup ? -1 : q;
        int o = (b * NGT + n) * 4 + (tid & 3);
        out[o]        = (float)sel;                    // src_idx
        out[512 + o]  = (sel >= 0) ? (float)n : -1.0f; // tgt_idx
        out[1024 + o] = (sel >= 0) ? 1.0f : 0.0f;      // valid
    }
}

extern "C" void kernel_launch(void* const* d_in, const int* in_sizes, int n_in,
                              void* d_out, int out_size) {
    const float* pm = (const float*)d_in[0];   // [4,200,256,256]
    const float* lg = (const float*)d_in[1];   // [4,200,2]
    const float* gt = (const float*)d_in[2];   // [4,32,256,256]
    float* out = (float*)d_out;

    const int smemA = (96 * STR) * sizeof(float);  // 50688 B
    cudaFuncSetAttribute(kA, cudaFuncAttributeMaxDynamicSharedMemorySize, smemA);

    kA<<<dim3(KS, 4, 4), 256, smemA>>>(pm, gt);
    kC<<<4, 256>>>(lg, out);
}